// round 13
// baseline (speedup 1.0000x reference)
#include <cuda_runtime.h>
#include <cstdint>

// FMFMNeuronInhib: T=4096, B=4096.  x:[T][B][2] f32.  out = spk|exc|inh|mem.
//
// Single-pass warp-specialized kernel. 148 blocks (all SMs) x 448 threads
// (14 warps), ragged neuron slices (blocks 0-99: 28 neurons, 100-147: 27),
// one block per SM, 112 KB dynamic smem:
//   warps  8-12 : cp.async-prefetch x chunk c+2 into a 3-deep smem ring
//   warp  13    : exact sequential mem recurrence from smem, mem -> smem ring
//   warps  0-3  : drain mem ring -> O_mem, O_spk (one chunk behind)
//   warps  4-7  : map staged x chunk -> O_exc, O_inh
// CH=128 steps/chunk (32 barrier periods). x read from DRAM exactly once;
// traffic = 384 MB. Fast path exact for winh==0; generic fallback otherwise.

#define T_STEPS 4096
#define B_NEUR  4096
#define CH      128                  // steps per smem chunk
#define NCH     (T_STEPS / CH)       // 32
#define XRING   3                    // x ring depth (prefetch 2 ahead)
#define THREADS 448
#define NLMAX   28                   // max neurons per block

#define XCHUNK_MAX (CH * NLMAX)                       // float2 per chunk (max)
#define XBYTES   (XRING * XCHUNK_MAX * 8)             // 86016 B
#define MBYTES   (2 * XCHUNK_MAX * 4)                 // 28672 B
#define SMEM_BYTES (XBYTES + MBYTES)                  // 114688 B

#define CP_ASYNC8(sa, g) \
    asm volatile("cp.async.ca.shared.global [%0], [%1], 8;" :: "r"(sa), "l"(g))
#define CP_COMMIT()  asm volatile("cp.async.commit_group;" ::: "memory")
#define CP_WAIT1()   asm volatile("cp.async.wait_group 1;" ::: "memory")

__global__ __launch_bounds__(THREADS, 1)
void fmfm_onepass(const float* __restrict__ x,
                  const float* __restrict__ w_exc,
                  const float* __restrict__ w_inh_p,
                  float* __restrict__ out)
{
    extern __shared__ char dynsmem[];
    float2* const xbuf   = reinterpret_cast<float2*>(dynsmem);           // [XRING][CH*nl]
    float*  const membuf = reinterpret_cast<float*>(dynsmem + XBYTES);   // [2][CH*nl]

    const int tid  = threadIdx.x;
    const int wid  = tid >> 5;
    const int lane = tid & 31;
    const int bid  = blockIdx.x;

    // ragged slice: blocks 0..99 -> 28 neurons, 100..147 -> 27
    const int nl = (bid < 100) ? 28 : 27;
    const int b0 = (bid < 100) ? bid * 28 : 2800 + (bid - 100) * 27;
    const int xchunk = CH * nl;              // float2 elems per staged chunk

    const float w00  = w_exc[0];
    const float w01  = w_exc[1];
    const float winh = *w_inh_p;

    float* __restrict__ O_spk = out;
    float* __restrict__ O_exc = out + (size_t)T_STEPS * B_NEUR;
    float* __restrict__ O_inh = out + 2ull * T_STEPS * B_NEUR;
    float* __restrict__ O_mem = out + 3ull * T_STEPS * B_NEUR;

    const float2* __restrict__ x2 = reinterpret_cast<const float2*>(x);
    const float2* __restrict__ xw = x2 + b0 + lane;   // valid only if lane < nl

    // ---------------- generic fallback (winh != 0): exact, never taken here
    if (winh != 0.0f) {
        if (tid < nl) {
            const int b = b0 + tid;
            const float2* __restrict__ xq = x2 + b;
            float mem = 0.0f, inh = 0.0f;
            for (int t = 0; t < T_STEPS; t++) {
                const float2 v = xq[(size_t)t * B_NEUR];
                inh = __fmaf_rn(0.6f, inh, v.x);
                const float exc = __fmaf_rn(v.y, w01, __fmul_rn(v.x, w00));
                const float cur = __fmaf_rn(winh, inh, exc);
                const float reset = (mem > 1.0f) ? 1.0f : 0.0f;
                mem = __fsub_rn(__fadd_rn(__fmul_rn(0.9f, mem), cur), reset);
                const size_t off = (size_t)t * B_NEUR + b;
                O_spk[off] = (__fsub_rn(mem, 1.0f) > 0.0f) ? 1.0f : 0.0f;
                O_exc[off] = exc;
                O_inh[off] = __fmul_rn(winh, inh);
                O_mem[off] = mem;
            }
        }
        return;
    }

    // ---------------- fast path (winh == 0) ----------------
    if (wid >= 8) {
        if (wid <= 12) {
            // ======== prefetch warps: cp.async chunk c+2 into ring ========
            const int p = wid - 8;
            if (lane < nl) {
                #pragma unroll
                for (int k = 0; k < 2; k++) {
                    float2* __restrict__ xb = xbuf + k * xchunk;
                    for (int s = p; s < CH; s += 5) {
                        const float2* g = xw + (size_t)(k * CH + s) * B_NEUR;
                        const uint32_t sa =
                            (uint32_t)__cvta_generic_to_shared(&xb[s * nl + lane]);
                        CP_ASYNC8(sa, g);
                    }
                    CP_COMMIT();
                }
            } else {
                CP_COMMIT(); CP_COMMIT();
            }
            CP_WAIT1();                 // chunk 0 resident
            __syncthreads();
            for (int c = 0; c < NCH; c++) {
                const int cf = c + 2;
                if (cf < NCH && lane < nl) {
                    const int t0 = cf * CH;
                    float2* __restrict__ xb = xbuf + (cf % XRING) * xchunk;
                    for (int s = p; s < CH; s += 5) {
                        const float2* g = xw + (size_t)(t0 + s) * B_NEUR;
                        const uint32_t sa =
                            (uint32_t)__cvta_generic_to_shared(&xb[s * nl + lane]);
                        CP_ASYNC8(sa, g);
                    }
                }
                CP_COMMIT();            // (possibly empty) group keeps indexing uniform
                CP_WAIT1();             // all but newest done -> chunk c+1 resident
                __syncthreads();
            }
        } else {
            // ======== chain warp (wid 13): exact mem recurrence ========
            float mem = 0.0f;
            __syncthreads();            // prologue barrier: chunk 0 staged
            for (int c = 0; c < NCH; c++) {
                const float2* __restrict__ xb = xbuf + (c % XRING) * xchunk;
                float* __restrict__       mb = membuf + (c & 1) * xchunk;
                if (lane < nl) {
                    #pragma unroll
                    for (int k = 0; k < CH; k += 16) {
                        float2 v[16];
                        #pragma unroll
                        for (int i = 0; i < 16; i++)
                            v[i] = xb[(k + i) * nl + lane];
                        #pragma unroll
                        for (int i = 0; i < 16; i++) {
                            // cur == exc exactly when winh==0
                            const float cur = __fmaf_rn(v[i].y, w01, __fmul_rn(v[i].x, w00));
                            const float reset = (mem > 1.0f) ? 1.0f : 0.0f;
                            mem = __fsub_rn(__fadd_rn(__fmul_rn(0.9f, mem), cur), reset);
                            mb[(k + i) * nl + lane] = mem;
                        }
                    }
                }
                __syncthreads();
            }
        }
    } else if (wid < 4) {
        // ======== mem/spk writers: drain chunk c-1 (32 steps per warp) ====
        const int w = wid;
        __syncthreads();                // prologue barrier
        for (int c = 0; c < NCH; c++) {
            if (c > 0 && lane < nl) {
                const float* __restrict__ mb = membuf + ((c - 1) & 1) * xchunk;
                const int t0 = (c - 1) * CH;
                #pragma unroll
                for (int s = w * 32; s < w * 32 + 32; s++) {
                    const float m = mb[s * nl + lane];
                    const size_t off = (size_t)(t0 + s) * B_NEUR + b0 + lane;
                    __stcs(O_mem + off, m);
                    __stcs(O_spk + off, (__fsub_rn(m, 1.0f) > 0.0f) ? 1.0f : 0.0f);
                }
            }
            __syncthreads();
        }
        if (lane < nl) {   // epilogue: last chunk
            const float* __restrict__ mb = membuf + ((NCH - 1) & 1) * xchunk;
            const int t0 = (NCH - 1) * CH;
            #pragma unroll
            for (int s = w * 32; s < w * 32 + 32; s++) {
                const float m = mb[s * nl + lane];
                const size_t off = (size_t)(t0 + s) * B_NEUR + b0 + lane;
                __stcs(O_mem + off, m);
                __stcs(O_spk + off, (__fsub_rn(m, 1.0f) > 0.0f) ? 1.0f : 0.0f);
            }
        }
    } else {
        // ======== exc/inh writers: map staged chunk c (32 steps per warp) ==
        const int w = wid - 4;
        __syncthreads();                // prologue barrier
        for (int c = 0; c < NCH; c++) {
            const float2* __restrict__ xb = xbuf + (c % XRING) * xchunk;
            const int t0 = c * CH;
            if (lane < nl) {
                #pragma unroll
                for (int s = w * 32; s < w * 32 + 32; s++) {
                    const float2 v = xb[s * nl + lane];
                    const float exc = __fmaf_rn(v.y, w01, __fmul_rn(v.x, w00));
                    const size_t off = (size_t)(t0 + s) * B_NEUR + b0 + lane;
                    __stcs(O_exc + off, exc);
                    __stcs(O_inh + off, 0.0f);   // winh==0: w_inh*inh == +0 exactly
                }
            }
            __syncthreads();
        }
    }
}

extern "C" void kernel_launch(void* const* d_in, const int* in_sizes, int n_in,
                              void* d_out, int out_size)
{
    const float* x     = (const float*)d_in[0];
    const float* w_exc = (const float*)d_in[1];
    const float* w_inh = (const float*)d_in[2];
    float* out         = (float*)d_out;
    (void)in_sizes; (void)n_in; (void)out_size;

    static int smem_set = 0;
    if (!smem_set) {
        cudaFuncSetAttribute(fmfm_onepass,
                             cudaFuncAttributeMaxDynamicSharedMemorySize,
                             SMEM_BYTES);
        smem_set = 1;
    }
    fmfm_onepass<<<148, THREADS, SMEM_BYTES>>>(x, w_exc, w_inh, out);
}

// round 14
// speedup vs baseline: 1.3178x; 1.3178x over previous
#include <cuda_runtime.h>
#include <cstdint>

// FMFMNeuronInhib: T=4096, B=4096.  x:[T][B][2] f32.  out = spk|exc|inh|mem.
//
// Single-pass warp-specialized kernel. 128 blocks x 448 threads (14 warps),
// 32 neurons per block (128B-aligned slices), one block per SM, 128 KB smem:
//   warps  8-12 : 16B cp.async-prefetch x chunk c+2 into a 3-deep smem ring
//   warp  13    : exact sequential mem recurrence from smem, mem -> smem ring
//   warps  0-3  : drain mem ring -> O_mem, O_spk   (LDS.128 + STG.128)
//   warps  4-7  : map staged x chunk -> O_exc, O_inh (LDS.128 + STG.128)
// All writer traffic is float4 (4 neurons/thread); LSU issue per period drops
// ~2.5x vs scalar STG.32. x read from DRAM exactly once; traffic = 384 MB.
// Fast path exact for winh==0 (fma(0,inh,exc)==exc, 0*inh==+0);
// generic winh!=0 handled by an exact (slow, never-taken here) fallback.

#define T_STEPS 4096
#define B_NEUR  4096
#define CH      128                  // steps per smem chunk
#define NCH     (T_STEPS / CH)       // 32
#define XRING   3                    // x ring depth (prefetch 2 ahead)
#define THREADS 448

#define XCHUNK_ELEMS (CH * 32)                        // float2 per chunk
#define XBYTES   (XRING * XCHUNK_ELEMS * 8)           // 96 KB
#define MBYTES   (2 * XCHUNK_ELEMS * 4)               // 32 KB
#define SMEM_BYTES (XBYTES + MBYTES)                  // 128 KB

#define CP_ASYNC16(sa, g) \
    asm volatile("cp.async.ca.shared.global [%0], [%1], 16;" :: "r"(sa), "l"(g))
#define CP_COMMIT()  asm volatile("cp.async.commit_group;" ::: "memory")
#define CP_WAIT1()   asm volatile("cp.async.wait_group 1;" ::: "memory")

__global__ __launch_bounds__(THREADS, 1)
void fmfm_onepass(const float* __restrict__ x,
                  const float* __restrict__ w_exc,
                  const float* __restrict__ w_inh_p,
                  float* __restrict__ out)
{
    extern __shared__ char dynsmem[];
    float2* const xbuf   = reinterpret_cast<float2*>(dynsmem);           // [XRING][CH*32]
    float*  const membuf = reinterpret_cast<float*>(dynsmem + XBYTES);   // [2][CH*32]

    const int tid  = threadIdx.x;
    const int wid  = tid >> 5;
    const int lane = tid & 31;
    const int b0   = blockIdx.x * 32;

    const float w00  = w_exc[0];
    const float w01  = w_exc[1];
    const float winh = *w_inh_p;

    float* __restrict__ O_spk = out;
    float* __restrict__ O_exc = out + (size_t)T_STEPS * B_NEUR;
    float* __restrict__ O_inh = out + 2ull * T_STEPS * B_NEUR;
    float* __restrict__ O_mem = out + 3ull * T_STEPS * B_NEUR;

    const float2* __restrict__ x2 = reinterpret_cast<const float2*>(x);

    // ---------------- generic fallback (winh != 0): exact, never taken here
    if (winh != 0.0f) {
        if (tid < 32) {
            const int b = b0 + tid;
            const float2* __restrict__ xq = x2 + b;
            float mem = 0.0f, inh = 0.0f;
            for (int t = 0; t < T_STEPS; t++) {
                const float2 v = xq[(size_t)t * B_NEUR];
                inh = __fmaf_rn(0.6f, inh, v.x);
                const float exc = __fmaf_rn(v.y, w01, __fmul_rn(v.x, w00));
                const float cur = __fmaf_rn(winh, inh, exc);
                const float reset = (mem > 1.0f) ? 1.0f : 0.0f;
                mem = __fsub_rn(__fadd_rn(__fmul_rn(0.9f, mem), cur), reset);
                const size_t off = (size_t)t * B_NEUR + b;
                O_spk[off] = (__fsub_rn(mem, 1.0f) > 0.0f) ? 1.0f : 0.0f;
                O_exc[off] = exc;
                O_inh[off] = __fmul_rn(winh, inh);
                O_mem[off] = mem;
            }
        }
        return;
    }

    // ---------------- fast path (winh == 0) ----------------
    if (wid >= 8) {
        if (wid <= 12) {
            // ======== prefetch warps: 16B cp.async, chunk c+2 into ring ====
            // lane -> (step-in-pair, neuron-pair): covers 2 steps x 32 neurons
            const int p    = wid - 8;
            const int sp   = lane >> 4;          // 0..1
            const int npr  = lane & 15;          // 0..15 (neurons 2*npr, 2*npr+1)
            const float2* __restrict__ gsrc = x2 + b0 + npr * 2;
            // prologue: chunks 0,1 -> one commit group each
            #pragma unroll
            for (int k = 0; k < 2; k++) {
                float2* __restrict__ xb = xbuf + k * XCHUNK_ELEMS;
                for (int s2 = p; s2 < CH / 2; s2 += 5) {
                    const int s = s2 * 2 + sp;
                    const float2* g = gsrc + (size_t)(k * CH + s) * B_NEUR;
                    const uint32_t sa =
                        (uint32_t)__cvta_generic_to_shared(&xb[s * 32 + npr * 2]);
                    CP_ASYNC16(sa, g);
                }
                CP_COMMIT();
            }
            CP_WAIT1();                 // chunk 0 resident
            __syncthreads();
            for (int c = 0; c < NCH; c++) {
                const int cf = c + 2;
                if (cf < NCH) {
                    const int t0 = cf * CH;
                    float2* __restrict__ xb = xbuf + (cf % XRING) * XCHUNK_ELEMS;
                    for (int s2 = p; s2 < CH / 2; s2 += 5) {
                        const int s = s2 * 2 + sp;
                        const float2* g = gsrc + (size_t)(t0 + s) * B_NEUR;
                        const uint32_t sa =
                            (uint32_t)__cvta_generic_to_shared(&xb[s * 32 + npr * 2]);
                        CP_ASYNC16(sa, g);
                    }
                }
                CP_COMMIT();            // (possibly empty) group keeps indexing uniform
                CP_WAIT1();             // all but newest done -> chunk c+1 resident
                __syncthreads();
            }
        } else {
            // ======== chain warp (wid 13): exact mem recurrence ========
            float mem = 0.0f;
            __syncthreads();            // prologue barrier: chunk 0 staged
            for (int c = 0; c < NCH; c++) {
                const float2* __restrict__ xb = xbuf + (c % XRING) * XCHUNK_ELEMS;
                float* __restrict__       mb = membuf + (c & 1) * XCHUNK_ELEMS;
                #pragma unroll
                for (int k = 0; k < CH; k += 16) {
                    float2 v[16];
                    #pragma unroll
                    for (int i = 0; i < 16; i++)
                        v[i] = xb[(k + i) * 32 + lane];
                    #pragma unroll
                    for (int i = 0; i < 16; i++) {
                        // cur == exc exactly when winh==0
                        const float cur = __fmaf_rn(v[i].y, w01, __fmul_rn(v[i].x, w00));
                        const float reset = (mem > 1.0f) ? 1.0f : 0.0f;
                        mem = __fsub_rn(__fadd_rn(__fmul_rn(0.9f, mem), cur), reset);
                        mb[(k + i) * 32 + lane] = mem;
                    }
                }
                __syncthreads();
            }
        }
    } else if (wid < 4) {
        // ======== mem/spk writers: drain chunk c-1, vectorized x4 ========
        // lane -> (step-in-quad, neuron-quad): 4 steps x 32 neurons per iter
        const int w  = wid;
        const int sl = lane >> 3;      // 0..3
        const int n4 = lane & 7;       // 0..7 (neurons 4*n4..4*n4+3)
        __syncthreads();               // prologue barrier
        for (int c = 0; c < NCH; c++) {
            if (c > 0) {
                const float4* __restrict__ mb4 = reinterpret_cast<const float4*>(
                    membuf + ((c - 1) & 1) * XCHUNK_ELEMS);
                const int t0 = (c - 1) * CH;
                #pragma unroll
                for (int it = 0; it < 8; it++) {
                    const int s = w * 32 + it * 4 + sl;
                    const float4 m4 = mb4[s * 8 + n4];
                    float4 sp;
                    sp.x = (__fsub_rn(m4.x, 1.0f) > 0.0f) ? 1.0f : 0.0f;
                    sp.y = (__fsub_rn(m4.y, 1.0f) > 0.0f) ? 1.0f : 0.0f;
                    sp.z = (__fsub_rn(m4.z, 1.0f) > 0.0f) ? 1.0f : 0.0f;
                    sp.w = (__fsub_rn(m4.w, 1.0f) > 0.0f) ? 1.0f : 0.0f;
                    const size_t off = (size_t)(t0 + s) * B_NEUR + b0 + n4 * 4;
                    __stcs(reinterpret_cast<float4*>(O_mem + off), m4);
                    __stcs(reinterpret_cast<float4*>(O_spk + off), sp);
                }
            }
            __syncthreads();
        }
        {   // epilogue: last chunk
            const float4* __restrict__ mb4 = reinterpret_cast<const float4*>(
                membuf + ((NCH - 1) & 1) * XCHUNK_ELEMS);
            const int t0 = (NCH - 1) * CH;
            #pragma unroll
            for (int it = 0; it < 8; it++) {
                const int s = w * 32 + it * 4 + sl;
                const float4 m4 = mb4[s * 8 + n4];
                float4 sp;
                sp.x = (__fsub_rn(m4.x, 1.0f) > 0.0f) ? 1.0f : 0.0f;
                sp.y = (__fsub_rn(m4.y, 1.0f) > 0.0f) ? 1.0f : 0.0f;
                sp.z = (__fsub_rn(m4.z, 1.0f) > 0.0f) ? 1.0f : 0.0f;
                sp.w = (__fsub_rn(m4.w, 1.0f) > 0.0f) ? 1.0f : 0.0f;
                const size_t off = (size_t)(t0 + s) * B_NEUR + b0 + n4 * 4;
                __stcs(reinterpret_cast<float4*>(O_mem + off), m4);
                __stcs(reinterpret_cast<float4*>(O_spk + off), sp);
            }
        }
    } else {
        // ======== exc/inh writers: map staged chunk c, vectorized x4 ======
        const int w  = wid - 4;
        const int sl = lane >> 3;      // 0..3
        const int n4 = lane & 7;       // 0..7
        const float4 z4 = make_float4(0.0f, 0.0f, 0.0f, 0.0f);
        __syncthreads();               // prologue barrier
        for (int c = 0; c < NCH; c++) {
            const float4* __restrict__ xb4 = reinterpret_cast<const float4*>(
                xbuf + (c % XRING) * XCHUNK_ELEMS);
            const int t0 = c * CH;
            #pragma unroll
            for (int it = 0; it < 8; it++) {
                const int s = w * 32 + it * 4 + sl;
                const float4 a = xb4[s * 16 + n4 * 2];        // neurons 4n4,4n4+1
                const float4 bq = xb4[s * 16 + n4 * 2 + 1];   // neurons 4n4+2,4n4+3
                float4 e;
                e.x = __fmaf_rn(a.y,  w01, __fmul_rn(a.x,  w00));
                e.y = __fmaf_rn(a.w,  w01, __fmul_rn(a.z,  w00));
                e.z = __fmaf_rn(bq.y, w01, __fmul_rn(bq.x, w00));
                e.w = __fmaf_rn(bq.w, w01, __fmul_rn(bq.z, w00));
                const size_t off = (size_t)(t0 + s) * B_NEUR + b0 + n4 * 4;
                __stcs(reinterpret_cast<float4*>(O_exc + off), e);
                __stcs(reinterpret_cast<float4*>(O_inh + off), z4); // winh==0 -> +0
            }
            __syncthreads();
        }
    }
}

extern "C" void kernel_launch(void* const* d_in, const int* in_sizes, int n_in,
                              void* d_out, int out_size)
{
    const float* x     = (const float*)d_in[0];
    const float* w_exc = (const float*)d_in[1];
    const float* w_inh = (const float*)d_in[2];
    float* out         = (float*)d_out;
    (void)in_sizes; (void)n_in; (void)out_size;

    static int smem_set = 0;
    if (!smem_set) {
        cudaFuncSetAttribute(fmfm_onepass,
                             cudaFuncAttributeMaxDynamicSharedMemorySize,
                             SMEM_BYTES);
        smem_set = 1;
    }
    fmfm_onepass<<<B_NEUR / 32, THREADS, SMEM_BYTES>>>(x, w_exc, w_inh, out);
}